// round 10
// baseline (speedup 1.0000x reference)
#include <cuda_runtime.h>

// Problem constants
#define L_SEQ   1024
#define BATCH   8
#define DM      512
#define NH      8
#define DH      64
#define M_ROWS  (L_SEQ * BATCH)   // 8192

// Scratch (allocation-free contract)
__device__ float g_q[64 * L_SEQ * DH];      // tf32-rounded q proj, [b*8+h][l][d]
__device__ float g_k[64 * L_SEQ * DH];
__device__ float g_v[64 * L_SEQ * DH];
__device__ float g_attn[M_ROWS * DM];       // tf32-rounded attn out, [l*8+b][h*64+d]
__device__ float g_xr[3 * M_ROWS * DM];     // tf32-rounded Q,K,V inputs
__device__ float g_wr[4 * DM * DM];         // tf32-rounded Wq,Wk,Wv,Wo

// ---------------------------------------------------------------------------
// TF32 + cp.async helpers
// ---------------------------------------------------------------------------
__device__ __forceinline__ unsigned f2tf(float x) {
    unsigned u; asm("cvt.rna.tf32.f32 %0, %1;" : "=r"(u) : "f"(x)); return u;
}
__device__ __forceinline__ float f2tf_f(float x) { return __uint_as_float(f2tf(x)); }
__device__ __forceinline__ unsigned U(float x) { return __float_as_uint(x); }

__device__ __forceinline__ void cpa16(void* dst, const void* src) {
    unsigned s = (unsigned)__cvta_generic_to_shared(dst);
    asm volatile("cp.async.ca.shared.global [%0], [%1], 16;" :: "r"(s), "l"(src));
}
#define CP_COMMIT() asm volatile("cp.async.commit_group;")
#define CP_WAIT0()  asm volatile("cp.async.wait_group 0;")
#define CP_WAIT1()  asm volatile("cp.async.wait_group 1;")

// D += A(16x8 row) * B(8x8 col), fp32 accum, tf32 inputs
__device__ __forceinline__ void mma8(float* d, const unsigned* a, const unsigned* b) {
    asm volatile("mma.sync.aligned.m16n8k8.row.col.f32.tf32.tf32.f32 "
        "{%0,%1,%2,%3}, {%4,%5,%6,%7}, {%8,%9}, {%0,%1,%2,%3};"
        : "+f"(d[0]), "+f"(d[1]), "+f"(d[2]), "+f"(d[3])
        : "r"(a[0]), "r"(a[1]), "r"(a[2]), "r"(a[3]), "r"(b[0]), "r"(b[1]));
}

// ---------------------------------------------------------------------------
// Pre-pass: tf32-round a tensor (float4 granularity)
// ---------------------------------------------------------------------------
__global__ void round_tf32(const float4* __restrict__ in, float4* __restrict__ out,
                           int n4)
{
    int i = blockIdx.x * blockDim.x + threadIdx.x;
    if (i < n4) {
        float4 t = in[i];
        t.x = f2tf_f(t.x); t.y = f2tf_f(t.y);
        t.z = f2tf_f(t.z); t.w = f2tf_f(t.w);
        out[i] = t;
    }
}

// ---------------------------------------------------------------------------
// TF32 GEMM, 2-stage cp.async pipeline: Y = X[M,512] @ W[512,512] + bias
// X and W are PRE-ROUNDED to tf32. Block 256 thr = 8 warps (4m x 2n),
// BM=128, BN=64, BK=16, warptile 32x32. Fragment layouts = round-6 (verified).
// mode 0: Y row-major [M,512] (fp32, unrounded)
// mode 1: Y scattered to [b*8+h][l][d], tf32-rounded (feeds attn)
// ---------------------------------------------------------------------------
#define XCH (128 * 20)
#define WCH (16 * 72)

__global__ __launch_bounds__(256)
void gemm_tc(const float* __restrict__ X, const float* __restrict__ W,
             const float* __restrict__ bias, float* __restrict__ Y, int mode)
{
    __shared__ float Xs[2][XCH];   // [row][k] stride 20
    __shared__ float Ws[2][WCH];   // [k][n]  stride 72

    const int tid  = threadIdx.x;
    const int lane = tid & 31;
    const int wid  = tid >> 5;
    const int wm   = wid & 3;
    const int wn   = wid >> 2;
    const int g    = lane >> 2;
    const int t4   = lane & 3;
    const int r0   = blockIdx.y * 128;
    const int n0   = blockIdx.x * 64;

    // fill-thread mapping
    const int xr0 = (tid * 2)     >> 2, xc0 = ((tid * 2)     & 3) * 4;
    const int xr1 = (tid * 2 + 1) >> 2, xc1 = ((tid * 2 + 1) & 3) * 4;
    const int wrow = tid >> 4;
    const int wc4  = (tid & 15) * 4;

    // prologue: fill chunk 0 into stage 0
    cpa16(&Xs[0][xr0 * 20 + xc0], &X[(r0 + xr0) * DM + xc0]);
    cpa16(&Xs[0][xr1 * 20 + xc1], &X[(r0 + xr1) * DM + xc1]);
    cpa16(&Ws[0][wrow * 72 + wc4], &W[wrow * DM + n0 + wc4]);
    CP_COMMIT();

    float acc[2][4][4];
#pragma unroll
    for (int mt = 0; mt < 2; mt++)
#pragma unroll
        for (int nt = 0; nt < 4; nt++)
#pragma unroll
            for (int i = 0; i < 4; i++) acc[mt][nt][i] = 0.f;

    for (int it = 0; it < 32; it++) {
        if (it < 31) {
            const int k0 = (it + 1) * 16;
            float* Xn = Xs[(it + 1) & 1];
            float* Wn = Ws[(it + 1) & 1];
            cpa16(&Xn[xr0 * 20 + xc0], &X[(r0 + xr0) * DM + k0 + xc0]);
            cpa16(&Xn[xr1 * 20 + xc1], &X[(r0 + xr1) * DM + k0 + xc1]);
            cpa16(&Wn[wrow * 72 + wc4], &W[(k0 + wrow) * DM + n0 + wc4]);
            CP_COMMIT();
            CP_WAIT1();     // chunk `it` complete; chunk it+1 in flight
        } else {
            CP_WAIT0();
        }
        __syncthreads();

        const float* Xb = Xs[it & 1];
        const float* Wb = Ws[it & 1];
#pragma unroll
        for (int k8 = 0; k8 < 2; k8++) {
            unsigned a[2][4];
#pragma unroll
            for (int mt = 0; mt < 2; mt++) {
                int rr = wm * 32 + mt * 16 + g;
                a[mt][0] = U(Xb[rr * 20       + k8 * 8 + t4    ]);
                a[mt][1] = U(Xb[(rr + 8) * 20 + k8 * 8 + t4    ]);
                a[mt][2] = U(Xb[rr * 20       + k8 * 8 + t4 + 4]);
                a[mt][3] = U(Xb[(rr + 8) * 20 + k8 * 8 + t4 + 4]);
            }
#pragma unroll
            for (int nt = 0; nt < 4; nt++) {
                unsigned bb[2];
                bb[0] = U(Wb[(k8 * 8 + t4) * 72     + wn * 32 + nt * 8 + g]);
                bb[1] = U(Wb[(k8 * 8 + t4 + 4) * 72 + wn * 32 + nt * 8 + g]);
                mma8(acc[0][nt], a[0], bb);
                mma8(acc[1][nt], a[1], bb);
            }
        }
        __syncthreads();   // all reads of stage it&1 done before it is refilled
    }

    // epilogue: bias + store
#pragma unroll
    for (int mt = 0; mt < 2; mt++) {
#pragma unroll
        for (int nt = 0; nt < 4; nt++) {
            int c  = n0 + wn * 32 + nt * 8 + 2 * t4;
            float b0 = bias[c], b1 = bias[c + 1];
            int rA = r0 + wm * 32 + mt * 16 + g;
            int rB = rA + 8;
            float2 vA, vB;
            if (mode == 0) {
                vA.x = acc[mt][nt][0] + b0; vA.y = acc[mt][nt][1] + b1;
                vB.x = acc[mt][nt][2] + b0; vB.y = acc[mt][nt][3] + b1;
                *(float2*)&Y[rA * DM + c] = vA;
                *(float2*)&Y[rB * DM + c] = vB;
            } else {
                // tf32-rounded for the attention consumer
                vA.x = f2tf_f(acc[mt][nt][0] + b0); vA.y = f2tf_f(acc[mt][nt][1] + b1);
                vB.x = f2tf_f(acc[mt][nt][2] + b0); vB.y = f2tf_f(acc[mt][nt][3] + b1);
                int h = c >> 6, d = c & 63;
                int lA = rA >> 3, bA = rA & 7;
                int lB = rB >> 3, bB = rB & 7;
                *(float2*)&Y[((bA * 8 + h) * L_SEQ + lA) * DH + d] = vA;
                *(float2*)&Y[((bB * 8 + h) * L_SEQ + lB) * DH + d] = vB;
            }
        }
    }
}

// ---------------------------------------------------------------------------
// Flash attention on tensor cores (round-6 structure, cvt-free fills).
// Inputs gq/gk/gv are pre-rounded tf32. Block 128 thr = 4 warps.
// Q-tile 64 rows, key tile 32. Warp w owns S/O rows 16w..16w+15.
// K tile filled via cp.async; V transposed via scalar stores (no cvt);
// P rounded with f2tf (8 values/thread/tile). grid: (L/64, 64 bh)
// ---------------------------------------------------------------------------
__global__ __launch_bounds__(128)
void attn_tc(const float* __restrict__ gq, const float* __restrict__ gk,
             const float* __restrict__ gv, float* __restrict__ out)
{
    __shared__ float Qs [64][68];   // [row][d]
    __shared__ float Ks [32][68];   // [key][d]  = B col-major for S
    __shared__ float Vst[64][37];   // [d][key]  = B col-major for PV
    __shared__ float Ps [64][36];   // [row][key] = A row-major for PV

    const int tid  = threadIdx.x;
    const int lane = tid & 31;
    const int w    = tid >> 5;
    const int g    = lane >> 2;
    const int t4   = lane & 3;
    const int bh   = blockIdx.y;
    const int b    = bh >> 3;
    const int h    = bh & 7;
    const float* qb = gq + bh * (L_SEQ * DH);
    const float* kb = gk + bh * (L_SEQ * DH);
    const float* vb = gv + bh * (L_SEQ * DH);
    const int q0 = blockIdx.x * 64;

    // fill Q tile: vectorized, scaled by 1/sqrt(64) (exact pow2; stays tf32)
#pragma unroll
    for (int i = 0; i < 8; i++) {
        int f4  = i * 128 + tid;
        int row = f4 >> 4;
        int c4  = (f4 & 15) * 4;
        float4 t = *(const float4*)&qb[(q0 + row) * DH + c4];
        t.x *= 0.125f; t.y *= 0.125f; t.z *= 0.125f; t.w *= 0.125f;
        *(float4*)&Qs[row][c4] = t;
    }

    const int rr0 = w * 16 + g;
    const int rr1 = rr0 + 8;

    float m0 = -1e30f, m1 = -1e30f, l0 = 0.f, l1 = 0.f;
    float acco[8][4];
#pragma unroll
    for (int j = 0; j < 8; j++)
#pragma unroll
        for (int i = 0; i < 4; i++) acco[j][i] = 0.f;

    for (int kt = 0; kt < L_SEQ / 32; kt++) {
        const int k0 = kt * 32;
        __syncthreads();   // prev PV done reading Vst/Ps; Qs visible (kt=0)

        // fill K via cp.async, V transposed via scalar stores
#pragma unroll
        for (int i = 0; i < 4; i++) {
            int f4  = i * 128 + tid;
            int key = f4 >> 4;
            int c4  = (f4 & 15) * 4;
            cpa16(&Ks[key][c4], &kb[(k0 + key) * DH + c4]);
            float4 vv = *(const float4*)&vb[(k0 + key) * DH + c4];
            Vst[c4 + 0][key] = vv.x;
            Vst[c4 + 1][key] = vv.y;
            Vst[c4 + 2][key] = vv.z;
            Vst[c4 + 3][key] = vv.w;
        }
        CP_COMMIT();
        CP_WAIT0();
        __syncthreads();

        // ---- S = Q.K^T ----
        float accs[4][4];
#pragma unroll
        for (int j = 0; j < 4; j++)
#pragma unroll
            for (int i = 0; i < 4; i++) accs[j][i] = 0.f;

#pragma unroll
        for (int k8 = 0; k8 < 8; k8++) {
            unsigned a[4];
            a[0] = U(Qs[rr0][k8 * 8 + t4    ]);
            a[1] = U(Qs[rr1][k8 * 8 + t4    ]);
            a[2] = U(Qs[rr0][k8 * 8 + t4 + 4]);
            a[3] = U(Qs[rr1][k8 * 8 + t4 + 4]);
#pragma unroll
            for (int j = 0; j < 4; j++) {
                unsigned bb[2];
                bb[0] = U(Ks[j * 8 + g][k8 * 8 + t4    ]);
                bb[1] = U(Ks[j * 8 + g][k8 * 8 + t4 + 4]);
                mma8(accs[j], a, bb);
            }
        }

        // ---- online softmax ----
        float tmax0 = -1e30f, tmax1 = -1e30f;
#pragma unroll
        for (int j = 0; j < 4; j++) {
            tmax0 = fmaxf(tmax0, fmaxf(accs[j][0], accs[j][1]));
            tmax1 = fmaxf(tmax1, fmaxf(accs[j][2], accs[j][3]));
        }
        tmax0 = fmaxf(tmax0, __shfl_xor_sync(0xffffffffu, tmax0, 1));
        tmax0 = fmaxf(tmax0, __shfl_xor_sync(0xffffffffu, tmax0, 2));
        tmax1 = fmaxf(tmax1, __shfl_xor_sync(0xffffffffu, tmax1, 1));
        tmax1 = fmaxf(tmax1, __shfl_xor_sync(0xffffffffu, tmax1, 2));

        float mn0 = fmaxf(m0, tmax0);
        float mn1 = fmaxf(m1, tmax1);
        float corr0 = __expf(m0 - mn0);
        float corr1 = __expf(m1 - mn1);
        m0 = mn0; m1 = mn1;

        float p[4][4];
        float ps0 = 0.f, ps1 = 0.f;
#pragma unroll
        for (int j = 0; j < 4; j++) {
            p[j][0] = __expf(accs[j][0] - mn0);
            p[j][1] = __expf(accs[j][1] - mn0);
            p[j][2] = __expf(accs[j][2] - mn1);
            p[j][3] = __expf(accs[j][3] - mn1);
            ps0 += p[j][0] + p[j][1];
            ps1 += p[j][2] + p[j][3];
        }
        ps0 += __shfl_xor_sync(0xffffffffu, ps0, 1);
        ps0 += __shfl_xor_sync(0xffffffffu, ps0, 2);
        ps1 += __shfl_xor_sync(0xffffffffu, ps1, 1);
        ps1 += __shfl_xor_sync(0xffffffffu, ps1, 2);
        l0 = l0 * corr0 + ps0;
        l1 = l1 * corr1 + ps1;

#pragma unroll
        for (int j = 0; j < 8; j++) {
            acco[j][0] *= corr0; acco[j][1] *= corr0;
            acco[j][2] *= corr1; acco[j][3] *= corr1;
        }

        // write P (tf32-rounded) in c-frag layout; own warp re-reads it
#pragma unroll
        for (int j = 0; j < 4; j++) {
            float2 pa; pa.x = f2tf_f(p[j][0]); pa.y = f2tf_f(p[j][1]);
            float2 pb; pb.x = f2tf_f(p[j][2]); pb.y = f2tf_f(p[j][3]);
            *(float2*)&Ps[rr0][j * 8 + 2 * t4] = pa;
            *(float2*)&Ps[rr1][j * 8 + 2 * t4] = pb;
        }
        __syncwarp();

        // ---- O += P.V ----
#pragma unroll
        for (int k8 = 0; k8 < 4; k8++) {
            unsigned a[4];
            a[0] = U(Ps[rr0][k8 * 8 + t4    ]);
            a[1] = U(Ps[rr1][k8 * 8 + t4    ]);
            a[2] = U(Ps[rr0][k8 * 8 + t4 + 4]);
            a[3] = U(Ps[rr1][k8 * 8 + t4 + 4]);
#pragma unroll
            for (int j = 0; j < 8; j++) {
                unsigned bb[2];
                bb[0] = U(Vst[j * 8 + g][k8 * 8 + t4    ]);
                bb[1] = U(Vst[j * 8 + g][k8 * 8 + t4 + 4]);
                mma8(acco[j], a, bb);
            }
        }
    }

    // epilogue: normalize, tf32-round (for the O-projection GEMM), store
    const float inv0 = 1.f / l0;
    const float inv1 = 1.f / l1;
    const int qg0 = q0 + rr0;
    const int qg1 = q0 + rr1;
#pragma unroll
    for (int j = 0; j < 8; j++) {
        int c = j * 8 + 2 * t4;
        float2 oa, ob;
        oa.x = f2tf_f(acco[j][0] * inv0); oa.y = f2tf_f(acco[j][1] * inv0);
        ob.x = f2tf_f(acco[j][2] * inv1); ob.y = f2tf_f(acco[j][3] * inv1);
        *(float2*)&out[(qg0 * 8 + b) * DM + h * DH + c] = oa;
        *(float2*)&out[(qg1 * 8 + b) * DM + h * DH + c] = ob;
    }
}

// ---------------------------------------------------------------------------
extern "C" void kernel_launch(void* const* d_in, const int* in_sizes, int n_in,
                              void* d_out, int out_size)
{
    const float* Q    = (const float*)d_in[0];
    const float* K    = (const float*)d_in[1];
    const float* V    = (const float*)d_in[2];
    const float* Wq   = (const float*)d_in[4];
    const float* bq   = (const float*)d_in[5];
    const float* Wk   = (const float*)d_in[6];
    const float* bk   = (const float*)d_in[7];
    const float* Wv   = (const float*)d_in[8];
    const float* bv   = (const float*)d_in[9];
    const float* Wo   = (const float*)d_in[10];
    const float* bo   = (const float*)d_in[11];
    float* out = (float*)d_out;

    float *gq, *gk, *gv, *gattn, *gxr, *gwr;
    cudaGetSymbolAddress((void**)&gq, g_q);
    cudaGetSymbolAddress((void**)&gk, g_k);
    cudaGetSymbolAddress((void**)&gv, g_v);
    cudaGetSymbolAddress((void**)&gattn, g_attn);
    cudaGetSymbolAddress((void**)&gxr, g_xr);
    cudaGetSymbolAddress((void**)&gwr, g_wr);

    const int NX = M_ROWS * DM;     // 4194304
    const int NW = DM * DM;         // 262144

    // pre-pass: tf32-round all mma inputs once
    round_tf32<<<NX / 4 / 256, 256>>>((const float4*)Q, (float4*)(gxr + 0 * NX), NX / 4);
    round_tf32<<<NX / 4 / 256, 256>>>((const float4*)K, (float4*)(gxr + 1 * NX), NX / 4);
    round_tf32<<<NX / 4 / 256, 256>>>((const float4*)V, (float4*)(gxr + 2 * NX), NX / 4);
    round_tf32<<<NW / 4 / 256, 256>>>((const float4*)Wq, (float4*)(gwr + 0 * NW), NW / 4);
    round_tf32<<<NW / 4 / 256, 256>>>((const float4*)Wk, (float4*)(gwr + 1 * NW), NW / 4);
    round_tf32<<<NW / 4 / 256, 256>>>((const float4*)Wv, (float4*)(gwr + 2 * NW), NW / 4);
    round_tf32<<<NW / 4 / 256, 256>>>((const float4*)Wo, (float4*)(gwr + 3 * NW), NW / 4);

    dim3 ggrid(DM / 64, M_ROWS / 128);   // (8, 64)
    gemm_tc<<<ggrid, 256>>>(gxr + 0 * NX, gwr + 0 * NW, bq, gq, 1);
    gemm_tc<<<ggrid, 256>>>(gxr + 1 * NX, gwr + 1 * NW, bk, gk, 1);
    gemm_tc<<<ggrid, 256>>>(gxr + 2 * NX, gwr + 2 * NW, bv, gv, 1);

    attn_tc<<<dim3(L_SEQ / 64, 64), 128>>>(gq, gk, gv, gattn);

    gemm_tc<<<ggrid, 256>>>(gattn, gwr + 3 * NW, bo, out, 0);
}

// round 11
// speedup vs baseline: 1.0583x; 1.0583x over previous
#include <cuda_runtime.h>

// Problem constants
#define L_SEQ   1024
#define BATCH   8
#define DM      512
#define NH      8
#define DH      64
#define M_ROWS  (L_SEQ * BATCH)   // 8192

// Scratch (allocation-free contract)
__device__ float g_q[64 * L_SEQ * DH];      // tf32-rounded q proj, [b*8+h][l][d]
__device__ float g_k[64 * L_SEQ * DH];
__device__ float g_v[64 * L_SEQ * DH];
__device__ float g_attn[M_ROWS * DM];       // tf32-rounded attn out, [l*8+b][h*64+d]
__device__ float g_xr[3 * M_ROWS * DM];     // tf32-rounded Q,K,V inputs
__device__ float g_wr[4 * DM * DM];         // tf32-rounded Wq,Wk,Wv,Wo

// ---------------------------------------------------------------------------
// TF32 + cp.async helpers
// ---------------------------------------------------------------------------
__device__ __forceinline__ unsigned f2tf(float x) {
    unsigned u; asm("cvt.rna.tf32.f32 %0, %1;" : "=r"(u) : "f"(x)); return u;
}
__device__ __forceinline__ float f2tf_f(float x) { return __uint_as_float(f2tf(x)); }
__device__ __forceinline__ unsigned U(float x) { return __float_as_uint(x); }

__device__ __forceinline__ void cpa16(void* dst, const void* src) {
    unsigned s = (unsigned)__cvta_generic_to_shared(dst);
    asm volatile("cp.async.ca.shared.global [%0], [%1], 16;" :: "r"(s), "l"(src));
}
#define CP_COMMIT() asm volatile("cp.async.commit_group;")
#define CP_WAIT0()  asm volatile("cp.async.wait_group 0;")
#define CP_WAIT1()  asm volatile("cp.async.wait_group 1;")

// D += A(16x8 row) * B(8x8 col), fp32 accum, tf32 inputs
__device__ __forceinline__ void mma8(float* d, const unsigned* a, const unsigned* b) {
    asm volatile("mma.sync.aligned.m16n8k8.row.col.f32.tf32.tf32.f32 "
        "{%0,%1,%2,%3}, {%4,%5,%6,%7}, {%8,%9}, {%0,%1,%2,%3};"
        : "+f"(d[0]), "+f"(d[1]), "+f"(d[2]), "+f"(d[3])
        : "r"(a[0]), "r"(a[1]), "r"(a[2]), "r"(a[3]), "r"(b[0]), "r"(b[1]));
}

// ---------------------------------------------------------------------------
// Pre-pass (ONE launch): tf32-round all 7 mma input tensors.
// blockIdx.y = segment: 0..2 -> Q,K,V (1M float4 each); 3..6 -> Wq,Wk,Wv,Wo
// (64K float4 each; excess blocks exit).
// ---------------------------------------------------------------------------
__global__ void round_all(const float4* __restrict__ Q, const float4* __restrict__ K,
                          const float4* __restrict__ V, const float4* __restrict__ Wq,
                          const float4* __restrict__ Wk, const float4* __restrict__ Wv,
                          const float4* __restrict__ Wo,
                          float4* __restrict__ xr, float4* __restrict__ wr)
{
    const int NX4 = M_ROWS * DM / 4;   // 1048576
    const int NW4 = DM * DM / 4;       // 65536
    const int seg = blockIdx.y;
    const float4* src;
    float4* dst;
    int n4;
    if (seg < 3) {
        src = (seg == 0) ? Q : (seg == 1) ? K : V;
        dst = xr + seg * NX4;
        n4  = NX4;
    } else {
        const int s = seg - 3;
        src = (s == 0) ? Wq : (s == 1) ? Wk : (s == 2) ? Wv : Wo;
        dst = wr + s * NW4;
        n4  = NW4;
    }
    int i = blockIdx.x * blockDim.x + threadIdx.x;
    if (i < n4) {
        float4 t = src[i];
        t.x = f2tf_f(t.x); t.y = f2tf_f(t.y);
        t.z = f2tf_f(t.z); t.w = f2tf_f(t.w);
        dst[i] = t;
    }
}

// ---------------------------------------------------------------------------
// TF32 GEMM core, 2-stage cp.async pipeline: Y = X[M,512] @ W[512,512] + bias
// X and W are PRE-ROUNDED to tf32. Block 256 thr = 8 warps (4m x 2n),
// BM=128, BN=64, BK=16, warptile 32x32.
// mode 0: Y row-major [M,512] (fp32, unrounded)
// mode 1: Y scattered to [b*8+h][l][d], tf32-rounded (feeds attn)
// ---------------------------------------------------------------------------
#define XCH (128 * 20)
#define WCH (16 * 72)

__device__ __forceinline__ void gemm_core(const float* __restrict__ X,
                                          const float* __restrict__ W,
                                          const float* __restrict__ bias,
                                          float* __restrict__ Y, int mode)
{
    __shared__ float Xs[2][XCH];   // [row][k] stride 20
    __shared__ float Ws[2][WCH];   // [k][n]  stride 72

    const int tid  = threadIdx.x;
    const int lane = tid & 31;
    const int wid  = tid >> 5;
    const int wm   = wid & 3;
    const int wn   = wid >> 2;
    const int g    = lane >> 2;
    const int t4   = lane & 3;
    const int r0   = blockIdx.y * 128;
    const int n0   = blockIdx.x * 64;

    const int xr0 = (tid * 2)     >> 2, xc0 = ((tid * 2)     & 3) * 4;
    const int xr1 = (tid * 2 + 1) >> 2, xc1 = ((tid * 2 + 1) & 3) * 4;
    const int wrow = tid >> 4;
    const int wc4  = (tid & 15) * 4;

    // prologue: fill chunk 0 into stage 0
    cpa16(&Xs[0][xr0 * 20 + xc0], &X[(r0 + xr0) * DM + xc0]);
    cpa16(&Xs[0][xr1 * 20 + xc1], &X[(r0 + xr1) * DM + xc1]);
    cpa16(&Ws[0][wrow * 72 + wc4], &W[wrow * DM + n0 + wc4]);
    CP_COMMIT();

    float acc[2][4][4];
#pragma unroll
    for (int mt = 0; mt < 2; mt++)
#pragma unroll
        for (int nt = 0; nt < 4; nt++)
#pragma unroll
            for (int i = 0; i < 4; i++) acc[mt][nt][i] = 0.f;

    for (int it = 0; it < 32; it++) {
        if (it < 31) {
            const int k0 = (it + 1) * 16;
            float* Xn = Xs[(it + 1) & 1];
            float* Wn = Ws[(it + 1) & 1];
            cpa16(&Xn[xr0 * 20 + xc0], &X[(r0 + xr0) * DM + k0 + xc0]);
            cpa16(&Xn[xr1 * 20 + xc1], &X[(r0 + xr1) * DM + k0 + xc1]);
            cpa16(&Wn[wrow * 72 + wc4], &W[(k0 + wrow) * DM + n0 + wc4]);
            CP_COMMIT();
            CP_WAIT1();     // chunk `it` complete; chunk it+1 in flight
        } else {
            CP_WAIT0();
        }
        __syncthreads();

        const float* Xb = Xs[it & 1];
        const float* Wb = Ws[it & 1];
#pragma unroll
        for (int k8 = 0; k8 < 2; k8++) {
            unsigned a[2][4];
#pragma unroll
            for (int mt = 0; mt < 2; mt++) {
                int rr = wm * 32 + mt * 16 + g;
                a[mt][0] = U(Xb[rr * 20       + k8 * 8 + t4    ]);
                a[mt][1] = U(Xb[(rr + 8) * 20 + k8 * 8 + t4    ]);
                a[mt][2] = U(Xb[rr * 20       + k8 * 8 + t4 + 4]);
                a[mt][3] = U(Xb[(rr + 8) * 20 + k8 * 8 + t4 + 4]);
            }
#pragma unroll
            for (int nt = 0; nt < 4; nt++) {
                unsigned bb[2];
                bb[0] = U(Wb[(k8 * 8 + t4) * 72     + wn * 32 + nt * 8 + g]);
                bb[1] = U(Wb[(k8 * 8 + t4 + 4) * 72 + wn * 32 + nt * 8 + g]);
                mma8(acc[0][nt], a[0], bb);
                mma8(acc[1][nt], a[1], bb);
            }
        }
        __syncthreads();   // all reads of stage it&1 done before it is refilled
    }

    // epilogue: bias + store
#pragma unroll
    for (int mt = 0; mt < 2; mt++) {
#pragma unroll
        for (int nt = 0; nt < 4; nt++) {
            int c  = n0 + wn * 32 + nt * 8 + 2 * t4;
            float b0 = bias[c], b1 = bias[c + 1];
            int rA = r0 + wm * 32 + mt * 16 + g;
            int rB = rA + 8;
            float2 vA, vB;
            if (mode == 0) {
                vA.x = acc[mt][nt][0] + b0; vA.y = acc[mt][nt][1] + b1;
                vB.x = acc[mt][nt][2] + b0; vB.y = acc[mt][nt][3] + b1;
                *(float2*)&Y[rA * DM + c] = vA;
                *(float2*)&Y[rB * DM + c] = vB;
            } else {
                vA.x = f2tf_f(acc[mt][nt][0] + b0); vA.y = f2tf_f(acc[mt][nt][1] + b1);
                vB.x = f2tf_f(acc[mt][nt][2] + b0); vB.y = f2tf_f(acc[mt][nt][3] + b1);
                int h = c >> 6, d = c & 63;
                int lA = rA >> 3, bA = rA & 7;
                int lB = rB >> 3, bB = rB & 7;
                *(float2*)&Y[((bA * 8 + h) * L_SEQ + lA) * DH + d] = vA;
                *(float2*)&Y[((bB * 8 + h) * L_SEQ + lB) * DH + d] = vB;
            }
        }
    }
}

// All 3 projection GEMMs in ONE launch: blockIdx.z selects X/W/bias/Y.
__global__ __launch_bounds__(256)
void gemm_proj3(const float* __restrict__ xr, const float* __restrict__ wr,
                const float* __restrict__ bq, const float* __restrict__ bk,
                const float* __restrict__ bv,
                float* __restrict__ gq, float* __restrict__ gk, float* __restrict__ gv)
{
    const int z = blockIdx.z;
    const float* X    = xr + z * (M_ROWS * DM);
    const float* W    = wr + z * (DM * DM);
    const float* bias = (z == 0) ? bq : (z == 1) ? bk : bv;
    float* Y          = (z == 0) ? gq : (z == 1) ? gk : gv;
    gemm_core(X, W, bias, Y, 1);
}

__global__ __launch_bounds__(256)
void gemm_out(const float* __restrict__ X, const float* __restrict__ W,
              const float* __restrict__ bias, float* __restrict__ Y)
{
    gemm_core(X, W, bias, Y, 0);
}

// ---------------------------------------------------------------------------
// Flash attention on tensor cores (round-6 structure, cvt-free fills).
// Inputs gq/gk/gv are pre-rounded tf32. Block 128 thr = 4 warps.
// Q-tile 64 rows, key tile 32. Warp w owns S/O rows 16w..16w+15.
// K tile filled via cp.async; V transposed via scalar stores.
// grid: (L/64, 64 bh)
// ---------------------------------------------------------------------------
__global__ __launch_bounds__(128)
void attn_tc(const float* __restrict__ gq, const float* __restrict__ gk,
             const float* __restrict__ gv, float* __restrict__ out)
{
    __shared__ float Qs [64][68];   // [row][d]
    __shared__ float Ks [32][68];   // [key][d]  = B col-major for S
    __shared__ float Vst[64][37];   // [d][key]  = B col-major for PV
    __shared__ float Ps [64][36];   // [row][key] = A row-major for PV

    const int tid  = threadIdx.x;
    const int lane = tid & 31;
    const int w    = tid >> 5;
    const int g    = lane >> 2;
    const int t4   = lane & 3;
    const int bh   = blockIdx.y;
    const int b    = bh >> 3;
    const int h    = bh & 7;
    const float* qb = gq + bh * (L_SEQ * DH);
    const float* kb = gk + bh * (L_SEQ * DH);
    const float* vb = gv + bh * (L_SEQ * DH);
    const int q0 = blockIdx.x * 64;

    // fill Q tile: vectorized, scaled by 1/sqrt(64) (exact pow2; stays tf32)
#pragma unroll
    for (int i = 0; i < 8; i++) {
        int f4  = i * 128 + tid;
        int row = f4 >> 4;
        int c4  = (f4 & 15) * 4;
        float4 t = *(const float4*)&qb[(q0 + row) * DH + c4];
        t.x *= 0.125f; t.y *= 0.125f; t.z *= 0.125f; t.w *= 0.125f;
        *(float4*)&Qs[row][c4] = t;
    }

    const int rr0 = w * 16 + g;
    const int rr1 = rr0 + 8;

    float m0 = -1e30f, m1 = -1e30f, l0 = 0.f, l1 = 0.f;
    float acco[8][4];
#pragma unroll
    for (int j = 0; j < 8; j++)
#pragma unroll
        for (int i = 0; i < 4; i++) acco[j][i] = 0.f;

    for (int kt = 0; kt < L_SEQ / 32; kt++) {
        const int k0 = kt * 32;
        __syncthreads();   // prev PV done reading Vst/Ps; Qs visible (kt=0)

        // fill K via cp.async, V transposed via scalar stores
#pragma unroll
        for (int i = 0; i < 4; i++) {
            int f4  = i * 128 + tid;
            int key = f4 >> 4;
            int c4  = (f4 & 15) * 4;
            cpa16(&Ks[key][c4], &kb[(k0 + key) * DH + c4]);
            float4 vv = *(const float4*)&vb[(k0 + key) * DH + c4];
            Vst[c4 + 0][key] = vv.x;
            Vst[c4 + 1][key] = vv.y;
            Vst[c4 + 2][key] = vv.z;
            Vst[c4 + 3][key] = vv.w;
        }
        CP_COMMIT();
        CP_WAIT0();
        __syncthreads();

        // ---- S = Q.K^T ----
        float accs[4][4];
#pragma unroll
        for (int j = 0; j < 4; j++)
#pragma unroll
            for (int i = 0; i < 4; i++) accs[j][i] = 0.f;

#pragma unroll
        for (int k8 = 0; k8 < 8; k8++) {
            unsigned a[4];
            a[0] = U(Qs[rr0][k8 * 8 + t4    ]);
            a[1] = U(Qs[rr1][k8 * 8 + t4    ]);
            a[2] = U(Qs[rr0][k8 * 8 + t4 + 4]);
            a[3] = U(Qs[rr1][k8 * 8 + t4 + 4]);
#pragma unroll
            for (int j = 0; j < 4; j++) {
                unsigned bb[2];
                bb[0] = U(Ks[j * 8 + g][k8 * 8 + t4    ]);
                bb[1] = U(Ks[j * 8 + g][k8 * 8 + t4 + 4]);
                mma8(accs[j], a, bb);
            }
        }

        // ---- online softmax ----
        float tmax0 = -1e30f, tmax1 = -1e30f;
#pragma unroll
        for (int j = 0; j < 4; j++) {
            tmax0 = fmaxf(tmax0, fmaxf(accs[j][0], accs[j][1]));
            tmax1 = fmaxf(tmax1, fmaxf(accs[j][2], accs[j][3]));
        }
        tmax0 = fmaxf(tmax0, __shfl_xor_sync(0xffffffffu, tmax0, 1));
        tmax0 = fmaxf(tmax0, __shfl_xor_sync(0xffffffffu, tmax0, 2));
        tmax1 = fmaxf(tmax1, __shfl_xor_sync(0xffffffffu, tmax1, 1));
        tmax1 = fmaxf(tmax1, __shfl_xor_sync(0xffffffffu, tmax1, 2));

        float mn0 = fmaxf(m0, tmax0);
        float mn1 = fmaxf(m1, tmax1);
        float corr0 = __expf(m0 - mn0);
        float corr1 = __expf(m1 - mn1);
        m0 = mn0; m1 = mn1;

        float p[4][4];
        float ps0 = 0.f, ps1 = 0.f;
#pragma unroll
        for (int j = 0; j < 4; j++) {
            p[j][0] = __expf(accs[j][0] - mn0);
            p[j][1] = __expf(accs[j][1] - mn0);
            p[j][2] = __expf(accs[j][2] - mn1);
            p[j][3] = __expf(accs[j][3] - mn1);
            ps0 += p[j][0] + p[j][1];
            ps1 += p[j][2] + p[j][3];
        }
        ps0 += __shfl_xor_sync(0xffffffffu, ps0, 1);
        ps0 += __shfl_xor_sync(0xffffffffu, ps0, 2);
        ps1 += __shfl_xor_sync(0xffffffffu, ps1, 1);
        ps1 += __shfl_xor_sync(0xffffffffu, ps1, 2);
        l0 = l0 * corr0 + ps0;
        l1 = l1 * corr1 + ps1;

#pragma unroll
        for (int j = 0; j < 8; j++) {
            acco[j][0] *= corr0; acco[j][1] *= corr0;
            acco[j][2] *= corr1; acco[j][3] *= corr1;
        }

        // write P (tf32-rounded) in c-frag layout; own warp re-reads it
#pragma unroll
        for (int j = 0; j < 4; j++) {
            float2 pa; pa.x = f2tf_f(p[j][0]); pa.y = f2tf_f(p[j][1]);
            float2 pb; pb.x = f2tf_f(p[j][2]); pb.y = f2tf_f(p[j][3]);
            *(float2*)&Ps[rr0][j * 8 + 2 * t4] = pa;
            *(float2*)&Ps[rr1][j * 8 + 2 * t4] = pb;
        }
        __syncwarp();

        // ---- O += P.V ----
#pragma unroll
        for (int k8 = 0; k8 < 4; k8++) {
            unsigned a[4];
            a[0] = U(Ps[rr0][k8 * 8 + t4    ]);
            a[1] = U(Ps[rr1][k8 * 8 + t4    ]);
            a[2] = U(Ps[rr0][k8 * 8 + t4 + 4]);
            a[3] = U(Ps[rr1][k8 * 8 + t4 + 4]);
#pragma unroll
            for (int j = 0; j < 8; j++) {
                unsigned bb[2];
                bb[0] = U(Vst[j * 8 + g][k8 * 8 + t4    ]);
                bb[1] = U(Vst[j * 8 + g][k8 * 8 + t4 + 4]);
                mma8(acco[j], a, bb);
            }
        }
    }

    // epilogue: normalize, tf32-round (for the O-projection GEMM), store
    const float inv0 = 1.f / l0;
    const float inv1 = 1.f / l1;
    const int qg0 = q0 + rr0;
    const int qg1 = q0 + rr1;
#pragma unroll
    for (int j = 0; j < 8; j++) {
        int c = j * 8 + 2 * t4;
        float2 oa, ob;
        oa.x = f2tf_f(acco[j][0] * inv0); oa.y = f2tf_f(acco[j][1] * inv0);
        ob.x = f2tf_f(acco[j][2] * inv1); ob.y = f2tf_f(acco[j][3] * inv1);
        *(float2*)&out[(qg0 * 8 + b) * DM + h * DH + c] = oa;
        *(float2*)&out[(qg1 * 8 + b) * DM + h * DH + c] = ob;
    }
}

// ---------------------------------------------------------------------------
extern "C" void kernel_launch(void* const* d_in, const int* in_sizes, int n_in,
                              void* d_out, int out_size)
{
    const float* Q    = (const float*)d_in[0];
    const float* K    = (const float*)d_in[1];
    const float* V    = (const float*)d_in[2];
    const float* Wq   = (const float*)d_in[4];
    const float* bq   = (const float*)d_in[5];
    const float* Wk   = (const float*)d_in[6];
    const float* bk   = (const float*)d_in[7];
    const float* Wv   = (const float*)d_in[8];
    const float* bv   = (const float*)d_in[9];
    const float* Wo   = (const float*)d_in[10];
    const float* bo   = (const float*)d_in[11];
    float* out = (float*)d_out;

    float *gq, *gk, *gv, *gattn, *gxr, *gwr;
    cudaGetSymbolAddress((void**)&gq, g_q);
    cudaGetSymbolAddress((void**)&gk, g_k);
    cudaGetSymbolAddress((void**)&gv, g_v);
    cudaGetSymbolAddress((void**)&gattn, g_attn);
    cudaGetSymbolAddress((void**)&gxr, g_xr);
    cudaGetSymbolAddress((void**)&gwr, g_wr);

    const int NX = M_ROWS * DM;     // 4194304

    // 1 launch: tf32-round all mma inputs (7 segments)
    round_all<<<dim3(NX / 4 / 256, 7), 256>>>(
        (const float4*)Q, (const float4*)K, (const float4*)V,
        (const float4*)Wq, (const float4*)Wk, (const float4*)Wv, (const float4*)Wo,
        (float4*)gxr, (float4*)gwr);

    // 1 launch: all 3 projection GEMMs
    gemm_proj3<<<dim3(DM / 64, M_ROWS / 128, 3), 256>>>(
        gxr, gwr, bq, bk, bv, gq, gk, gv);

    // 1 launch: attention
    attn_tc<<<dim3(L_SEQ / 64, 64), 128>>>(gq, gk, gv, gattn);

    // 1 launch: output projection
    gemm_out<<<dim3(DM / 64, M_ROWS / 128), 256>>>(
        gattn, gwr + 3 * (DM * DM), bo, out);
}

// round 12
// speedup vs baseline: 1.2800x; 1.2095x over previous
#include <cuda_runtime.h>

// Problem constants
#define L_SEQ   1024
#define BATCH   8
#define DM      512
#define NH      8
#define DH      64
#define M_ROWS  (L_SEQ * BATCH)   // 8192

// Scratch (allocation-free contract)
__device__ float g_q[64 * L_SEQ * DH];      // tf32-rounded q proj, [b*8+h][l][d]
__device__ float g_k[64 * L_SEQ * DH];
__device__ float g_v[64 * L_SEQ * DH];
__device__ float g_attn[M_ROWS * DM];       // tf32-rounded attn out, [l*8+b][h*64+d]
__device__ float g_xr[3 * M_ROWS * DM];     // tf32-rounded Q,K,V inputs
__device__ float g_wr[4 * DM * DM];         // tf32-rounded Wq,Wk,Wv,Wo

// ---------------------------------------------------------------------------
// TF32 + cp.async helpers
// ---------------------------------------------------------------------------
__device__ __forceinline__ unsigned f2tf(float x) {
    unsigned u; asm("cvt.rna.tf32.f32 %0, %1;" : "=r"(u) : "f"(x)); return u;
}
__device__ __forceinline__ float f2tf_f(float x) { return __uint_as_float(f2tf(x)); }
__device__ __forceinline__ unsigned U(float x) { return __float_as_uint(x); }

__device__ __forceinline__ void cpa16(void* dst, const void* src) {
    unsigned s = (unsigned)__cvta_generic_to_shared(dst);
    asm volatile("cp.async.ca.shared.global [%0], [%1], 16;" :: "r"(s), "l"(src));
}
#define CP_COMMIT() asm volatile("cp.async.commit_group;")
#define CP_WAIT0()  asm volatile("cp.async.wait_group 0;")
#define CP_WAIT1()  asm volatile("cp.async.wait_group 1;")

// D += A(16x8 row) * B(8x8 col), fp32 accum, tf32 inputs
__device__ __forceinline__ void mma8(float* d, const unsigned* a, const unsigned* b) {
    asm volatile("mma.sync.aligned.m16n8k8.row.col.f32.tf32.tf32.f32 "
        "{%0,%1,%2,%3}, {%4,%5,%6,%7}, {%8,%9}, {%0,%1,%2,%3};"
        : "+f"(d[0]), "+f"(d[1]), "+f"(d[2]), "+f"(d[3])
        : "r"(a[0]), "r"(a[1]), "r"(a[2]), "r"(a[3]), "r"(b[0]), "r"(b[1]));
}

// ---------------------------------------------------------------------------
// Pre-pass (ONE launch): tf32-round all 7 mma input tensors.
// blockIdx.y = segment: 0..2 -> Q,K,V; 3..6 -> Wq,Wk,Wv,Wo (excess blocks exit)
// ---------------------------------------------------------------------------
__global__ void round_all(const float4* __restrict__ Q, const float4* __restrict__ K,
                          const float4* __restrict__ V, const float4* __restrict__ Wq,
                          const float4* __restrict__ Wk, const float4* __restrict__ Wv,
                          const float4* __restrict__ Wo,
                          float4* __restrict__ xr, float4* __restrict__ wr)
{
    const int NX4 = M_ROWS * DM / 4;   // 1048576
    const int NW4 = DM * DM / 4;       // 65536
    const int seg = blockIdx.y;
    const float4* src;
    float4* dst;
    int n4;
    if (seg < 3) {
        src = (seg == 0) ? Q : (seg == 1) ? K : V;
        dst = xr + seg * NX4;
        n4  = NX4;
    } else {
        const int s = seg - 3;
        src = (s == 0) ? Wq : (s == 1) ? Wk : (s == 2) ? Wv : Wo;
        dst = wr + s * NW4;
        n4  = NW4;
    }
    int i = blockIdx.x * blockDim.x + threadIdx.x;
    if (i < n4) {
        float4 t = src[i];
        t.x = f2tf_f(t.x); t.y = f2tf_f(t.y);
        t.z = f2tf_f(t.z); t.w = f2tf_f(t.w);
        dst[i] = t;
    }
}

// ---------------------------------------------------------------------------
// TF32 GEMM core, 2-stage cp.async pipeline: Y = X[M,512] @ W[512,512] + bias
// Block tile 128x128, BK=16. 8 warps (4m x 2n), warptile 32x64:
// 32 mmas per warp per sync (2x the old BN=64 version).
// mode 0: Y row-major [M,512] (fp32); mode 1: scatter tf32 to [b*8+h][l][d]
// ---------------------------------------------------------------------------
#define XST 20
#define WST 136
#define XCH (128 * XST)
#define WCH (16 * WST)

__device__ __forceinline__ void gemm_core(const float* __restrict__ X,
                                          const float* __restrict__ W,
                                          const float* __restrict__ bias,
                                          float* __restrict__ Y, int mode)
{
    __shared__ float Xs[2][XCH];   // [row][k] stride 20
    __shared__ float Ws[2][WCH];   // [k][n]  stride 136 (128 cols + 8 pad)

    const int tid  = threadIdx.x;
    const int lane = tid & 31;
    const int wid  = tid >> 5;
    const int wm   = wid & 3;       // 32-row slab
    const int wn   = wid >> 2;      // 64-col slab
    const int g    = lane >> 2;
    const int t4   = lane & 3;
    const int r0   = blockIdx.y * 128;
    const int n0   = blockIdx.x * 128;

    // fill-thread mapping (X: 512 f4/chunk, W: 512 f4/chunk; 2 each per thread)
    const int xr0 = (tid * 2)     >> 2, xc0 = ((tid * 2)     & 3) * 4;
    const int xr1 = (tid * 2 + 1) >> 2, xc1 = ((tid * 2 + 1) & 3) * 4;
    const int wr0 = tid >> 5,           wc0 = (tid & 31) * 4;         // rows 0..7
    const int wr1 = 8 + wr0;                                          // rows 8..15

    // prologue: fill chunk 0 into stage 0
    cpa16(&Xs[0][xr0 * XST + xc0], &X[(r0 + xr0) * DM + xc0]);
    cpa16(&Xs[0][xr1 * XST + xc1], &X[(r0 + xr1) * DM + xc1]);
    cpa16(&Ws[0][wr0 * WST + wc0], &W[wr0 * DM + n0 + wc0]);
    cpa16(&Ws[0][wr1 * WST + wc0], &W[wr1 * DM + n0 + wc0]);
    CP_COMMIT();

    float acc[2][8][4];
#pragma unroll
    for (int mt = 0; mt < 2; mt++)
#pragma unroll
        for (int nt = 0; nt < 8; nt++)
#pragma unroll
            for (int i = 0; i < 4; i++) acc[mt][nt][i] = 0.f;

    for (int it = 0; it < 32; it++) {
        if (it < 31) {
            const int k0 = (it + 1) * 16;
            float* Xn = Xs[(it + 1) & 1];
            float* Wn = Ws[(it + 1) & 1];
            cpa16(&Xn[xr0 * XST + xc0], &X[(r0 + xr0) * DM + k0 + xc0]);
            cpa16(&Xn[xr1 * XST + xc1], &X[(r0 + xr1) * DM + k0 + xc1]);
            cpa16(&Wn[wr0 * WST + wc0], &W[(k0 + wr0) * DM + n0 + wc0]);
            cpa16(&Wn[wr1 * WST + wc0], &W[(k0 + wr1) * DM + n0 + wc0]);
            CP_COMMIT();
            CP_WAIT1();     // chunk `it` complete; chunk it+1 in flight
        } else {
            CP_WAIT0();
        }
        __syncthreads();

        const float* Xb = Xs[it & 1];
        const float* Wb = Ws[it & 1];
#pragma unroll
        for (int k8 = 0; k8 < 2; k8++) {
            unsigned a[2][4];
#pragma unroll
            for (int mt = 0; mt < 2; mt++) {
                int rr = wm * 32 + mt * 16 + g;
                a[mt][0] = U(Xb[rr * XST       + k8 * 8 + t4    ]);
                a[mt][1] = U(Xb[(rr + 8) * XST + k8 * 8 + t4    ]);
                a[mt][2] = U(Xb[rr * XST       + k8 * 8 + t4 + 4]);
                a[mt][3] = U(Xb[(rr + 8) * XST + k8 * 8 + t4 + 4]);
            }
#pragma unroll
            for (int nt = 0; nt < 8; nt++) {
                unsigned bb[2];
                bb[0] = U(Wb[(k8 * 8 + t4) * WST     + wn * 64 + nt * 8 + g]);
                bb[1] = U(Wb[(k8 * 8 + t4 + 4) * WST + wn * 64 + nt * 8 + g]);
                mma8(acc[0][nt], a[0], bb);
                mma8(acc[1][nt], a[1], bb);
            }
        }
        __syncthreads();   // all reads of stage it&1 done before it is refilled
    }

    // epilogue: bias + store
#pragma unroll
    for (int mt = 0; mt < 2; mt++) {
#pragma unroll
        for (int nt = 0; nt < 8; nt++) {
            int c  = n0 + wn * 64 + nt * 8 + 2 * t4;
            float b0 = bias[c], b1 = bias[c + 1];
            int rA = r0 + wm * 32 + mt * 16 + g;
            int rB = rA + 8;
            float2 vA, vB;
            if (mode == 0) {
                vA.x = acc[mt][nt][0] + b0; vA.y = acc[mt][nt][1] + b1;
                vB.x = acc[mt][nt][2] + b0; vB.y = acc[mt][nt][3] + b1;
                *(float2*)&Y[rA * DM + c] = vA;
                *(float2*)&Y[rB * DM + c] = vB;
            } else {
                vA.x = f2tf_f(acc[mt][nt][0] + b0); vA.y = f2tf_f(acc[mt][nt][1] + b1);
                vB.x = f2tf_f(acc[mt][nt][2] + b0); vB.y = f2tf_f(acc[mt][nt][3] + b1);
                int h = c >> 6, d = c & 63;
                int lA = rA >> 3, bA = rA & 7;
                int lB = rB >> 3, bB = rB & 7;
                *(float2*)&Y[((bA * 8 + h) * L_SEQ + lA) * DH + d] = vA;
                *(float2*)&Y[((bB * 8 + h) * L_SEQ + lB) * DH + d] = vB;
            }
        }
    }
}

// All 3 projection GEMMs in ONE launch: blockIdx.z selects X/W/bias/Y.
__global__ __launch_bounds__(256)
void gemm_proj3(const float* __restrict__ xr, const float* __restrict__ wr,
                const float* __restrict__ bq, const float* __restrict__ bk,
                const float* __restrict__ bv,
                float* __restrict__ gq, float* __restrict__ gk, float* __restrict__ gv)
{
    const int z = blockIdx.z;
    const float* X    = xr + z * (M_ROWS * DM);
    const float* W    = wr + z * (DM * DM);
    const float* bias = (z == 0) ? bq : (z == 1) ? bk : bv;
    float* Y          = (z == 0) ? gq : (z == 1) ? gk : gv;
    gemm_core(X, W, bias, Y, 1);
}

__global__ __launch_bounds__(256)
void gemm_out(const float* __restrict__ X, const float* __restrict__ W,
              const float* __restrict__ bias, float* __restrict__ Y)
{
    gemm_core(X, W, bias, Y, 0);
}

// ---------------------------------------------------------------------------
// Flash attention on tensor cores. Inputs pre-rounded tf32.
// V kept ROW-MAJOR [key][d] stride 72 — for O += P.V the mma B-fragment is
// exactly V[k8*8+t4][j*8+g]; banks (8*t4+g) mod 32 = all distinct. Both K and
// V tiles fill via cp.async (no transpose, no scalar stores).
// Block 128 thr = 4 warps; Q-tile 64 rows, key tile 32. grid: (L/64, 64 bh)
// ---------------------------------------------------------------------------
__global__ __launch_bounds__(128)
void attn_tc(const float* __restrict__ gq, const float* __restrict__ gk,
             const float* __restrict__ gv, float* __restrict__ out)
{
    __shared__ float Qs[64][68];   // [row][d]
    __shared__ float Ks[32][68];   // [key][d] = B col-major for S
    __shared__ float Vs[32][72];   // [key][d] row-major = B col-major for PV
    __shared__ float Ps[64][36];   // [row][key] = A row-major for PV

    const int tid  = threadIdx.x;
    const int lane = tid & 31;
    const int w    = tid >> 5;
    const int g    = lane >> 2;
    const int t4   = lane & 3;
    const int bh   = blockIdx.y;
    const int b    = bh >> 3;
    const int h    = bh & 7;
    const float* qb = gq + bh * (L_SEQ * DH);
    const float* kb = gk + bh * (L_SEQ * DH);
    const float* vb = gv + bh * (L_SEQ * DH);
    const int q0 = blockIdx.x * 64;

    // fill Q tile: vectorized, scaled by 1/sqrt(64) (exact pow2; stays tf32)
#pragma unroll
    for (int i = 0; i < 8; i++) {
        int f4  = i * 128 + tid;
        int row = f4 >> 4;
        int c4  = (f4 & 15) * 4;
        float4 t = *(const float4*)&qb[(q0 + row) * DH + c4];
        t.x *= 0.125f; t.y *= 0.125f; t.z *= 0.125f; t.w *= 0.125f;
        *(float4*)&Qs[row][c4] = t;
    }

    const int rr0 = w * 16 + g;
    const int rr1 = rr0 + 8;

    float m0 = -1e30f, m1 = -1e30f, l0 = 0.f, l1 = 0.f;
    float acco[8][4];
#pragma unroll
    for (int j = 0; j < 8; j++)
#pragma unroll
        for (int i = 0; i < 4; i++) acco[j][i] = 0.f;

    for (int kt = 0; kt < L_SEQ / 32; kt++) {
        const int k0 = kt * 32;
        __syncthreads();   // prev PV done reading Vs/Ps; Qs visible (kt=0)

        // fill K and V tiles via cp.async (4 f4 each per thread)
#pragma unroll
        for (int i = 0; i < 4; i++) {
            int f4  = i * 128 + tid;
            int key = f4 >> 4;
            int c4  = (f4 & 15) * 4;
            cpa16(&Ks[key][c4], &kb[(k0 + key) * DH + c4]);
            cpa16(&Vs[key][c4], &vb[(k0 + key) * DH + c4]);
        }
        CP_COMMIT();
        CP_WAIT0();
        __syncthreads();

        // ---- S = Q.K^T ----
        float accs[4][4];
#pragma unroll
        for (int j = 0; j < 4; j++)
#pragma unroll
            for (int i = 0; i < 4; i++) accs[j][i] = 0.f;

#pragma unroll
        for (int k8 = 0; k8 < 8; k8++) {
            unsigned a[4];
            a[0] = U(Qs[rr0][k8 * 8 + t4    ]);
            a[1] = U(Qs[rr1][k8 * 8 + t4    ]);
            a[2] = U(Qs[rr0][k8 * 8 + t4 + 4]);
            a[3] = U(Qs[rr1][k8 * 8 + t4 + 4]);
#pragma unroll
            for (int j = 0; j < 4; j++) {
                unsigned bb[2];
                bb[0] = U(Ks[j * 8 + g][k8 * 8 + t4    ]);
                bb[1] = U(Ks[j * 8 + g][k8 * 8 + t4 + 4]);
                mma8(accs[j], a, bb);
            }
        }

        // ---- online softmax ----
        float tmax0 = -1e30f, tmax1 = -1e30f;
#pragma unroll
        for (int j = 0; j < 4; j++) {
            tmax0 = fmaxf(tmax0, fmaxf(accs[j][0], accs[j][1]));
            tmax1 = fmaxf(tmax1, fmaxf(accs[j][2], accs[j][3]));
        }
        tmax0 = fmaxf(tmax0, __shfl_xor_sync(0xffffffffu, tmax0, 1));
        tmax0 = fmaxf(tmax0, __shfl_xor_sync(0xffffffffu, tmax0, 2));
        tmax1 = fmaxf(tmax1, __shfl_xor_sync(0xffffffffu, tmax1, 1));
        tmax1 = fmaxf(tmax1, __shfl_xor_sync(0xffffffffu, tmax1, 2));

        float mn0 = fmaxf(m0, tmax0);
        float mn1 = fmaxf(m1, tmax1);
        float corr0 = __expf(m0 - mn0);
        float corr1 = __expf(m1 - mn1);
        m0 = mn0; m1 = mn1;

        float p[4][4];
        float ps0 = 0.f, ps1 = 0.f;
#pragma unroll
        for (int j = 0; j < 4; j++) {
            p[j][0] = __expf(accs[j][0] - mn0);
            p[j][1] = __expf(accs[j][1] - mn0);
            p[j][2] = __expf(accs[j][2] - mn1);
            p[j][3] = __expf(accs[j][3] - mn1);
            ps0 += p[j][0] + p[j][1];
            ps1 += p[j][2] + p[j][3];
        }
        ps0 += __shfl_xor_sync(0xffffffffu, ps0, 1);
        ps0 += __shfl_xor_sync(0xffffffffu, ps0, 2);
        ps1 += __shfl_xor_sync(0xffffffffu, ps1, 1);
        ps1 += __shfl_xor_sync(0xffffffffu, ps1, 2);
        l0 = l0 * corr0 + ps0;
        l1 = l1 * corr1 + ps1;

#pragma unroll
        for (int j = 0; j < 8; j++) {
            acco[j][0] *= corr0; acco[j][1] *= corr0;
            acco[j][2] *= corr1; acco[j][3] *= corr1;
        }

        // write P (tf32-rounded) in c-frag layout; own warp re-reads it
#pragma unroll
        for (int j = 0; j < 4; j++) {
            float2 pa; pa.x = f2tf_f(p[j][0]); pa.y = f2tf_f(p[j][1]);
            float2 pb; pb.x = f2tf_f(p[j][2]); pb.y = f2tf_f(p[j][3]);
            *(float2*)&Ps[rr0][j * 8 + 2 * t4] = pa;
            *(float2*)&Ps[rr1][j * 8 + 2 * t4] = pb;
        }
        __syncwarp();

        // ---- O += P.V  (B frag = row-major V directly) ----
#pragma unroll
        for (int k8 = 0; k8 < 4; k8++) {
            unsigned a[4];
            a[0] = U(Ps[rr0][k8 * 8 + t4    ]);
            a[1] = U(Ps[rr1][k8 * 8 + t4    ]);
            a[2] = U(Ps[rr0][k8 * 8 + t4 + 4]);
            a[3] = U(Ps[rr1][k8 * 8 + t4 + 4]);
#pragma unroll
            for (int j = 0; j < 8; j++) {
                unsigned bb[2];
                bb[0] = U(Vs[k8 * 8 + t4    ][j * 8 + g]);
                bb[1] = U(Vs[k8 * 8 + t4 + 4][j * 8 + g]);
                mma8(acco[j], a, bb);
            }
        }
    }

    // epilogue: normalize, tf32-round (for the O-projection GEMM), store
    const float inv0 = 1.f / l0;
    const float inv1 = 1.f / l1;
    const int qg0 = q0 + rr0;
    const int qg1 = q0 + rr1;
#pragma unroll
    for (int j = 0; j < 8; j++) {
        int c = j * 8 + 2 * t4;
        float2 oa, ob;
        oa.x = f2tf_f(acco[j][0] * inv0); oa.y = f2tf_f(acco[j][1] * inv0);
        ob.x = f2tf_f(acco[j][2] * inv1); ob.y = f2tf_f(acco[j][3] * inv1);
        *(float2*)&out[(qg0 * 8 + b) * DM + h * DH + c] = oa;
        *(float2*)&out[(qg1 * 8 + b) * DM + h * DH + c] = ob;
    }
}

// ---------------------------------------------------------------------------
extern "C" void kernel_launch(void* const* d_in, const int* in_sizes, int n_in,
                              void* d_out, int out_size)
{
    const float* Q    = (const float*)d_in[0];
    const float* K    = (const float*)d_in[1];
    const float* V    = (const float*)d_in[2];
    const float* Wq   = (const float*)d_in[4];
    const float* bq   = (const float*)d_in[5];
    const float* Wk   = (const float*)d_in[6];
    const float* bk   = (const float*)d_in[7];
    const float* Wv   = (const float*)d_in[8];
    const float* bv   = (const float*)d_in[9];
    const float* Wo   = (const float*)d_in[10];
    const float* bo   = (const float*)d_in[11];
    float* out = (float*)d_out;

    float *gq, *gk, *gv, *gattn, *gxr, *gwr;
    cudaGetSymbolAddress((void**)&gq, g_q);
    cudaGetSymbolAddress((void**)&gk, g_k);
    cudaGetSymbolAddress((void**)&gv, g_v);
    cudaGetSymbolAddress((void**)&gattn, g_attn);
    cudaGetSymbolAddress((void**)&gxr, g_xr);
    cudaGetSymbolAddress((void**)&gwr, g_wr);

    const int NX = M_ROWS * DM;     // 4194304

    // 1 launch: tf32-round all mma inputs (7 segments)
    round_all<<<dim3(NX / 4 / 256, 7), 256>>>(
        (const float4*)Q, (const float4*)K, (const float4*)V,
        (const float4*)Wq, (const float4*)Wk, (const float4*)Wv, (const float4*)Wo,
        (float4*)gxr, (float4*)gwr);

    // 1 launch: all 3 projection GEMMs (block tile 128x128)
    gemm_proj3<<<dim3(DM / 128, M_ROWS / 128, 3), 256>>>(
        gxr, gwr, bq, bk, bv, gq, gk, gv);

    // 1 launch: attention
    attn_tc<<<dim3(L_SEQ / 64, 64), 128>>>(gq, gk, gv, gattn);

    // 1 launch: output projection
    gemm_out<<<dim3(DM / 128, M_ROWS / 128), 256>>>(
        gattn, gwr + 3 * (DM * DM), bo, out);
}